// round 6
// baseline (speedup 1.0000x reference)
#include <cuda_runtime.h>

__device__ double g_rot_acc[64];
__device__ double g_str_acc[64];
__device__ unsigned int g_ticket = 0;

#define TPB 128
#define PPT 8
#define FULLMASK 0xffffffffu

// Branch-free atan2 (cephes core), abs err ~1e-7 rad, 1 MUFU.RCP.
__device__ __forceinline__ float fast_atan2f(float y, float x) {
    float ay = fabsf(y), ax = fabsf(x);
    float mn = fminf(ay, ax), mx = fmaxf(ay, ax);
    bool  big = mn > 0.41421356237f * mx;
    float num = big ? (mn - mx) : mn;
    float den = big ? (mn + mx) : mx;
    float z = __fdividef(num, den);
    float s = z * z;
    float p = fmaf(fmaf(fmaf(fmaf(8.05374449538e-2f, s, -1.38776856032e-1f), s,
                             1.99777106478e-1f), s, -3.33329491539e-1f),
                   s * z, z);
    float r = big ? (0.78539816339744831f + p) : p;
    if (ay > ax) r = 1.57079632679489662f - r;
    if (x < 0.0f) r = 3.14159265358979323f - r;
    return copysignf(r, y);
}

struct Hd { float d1x, d1y, d2x, d2y, e; };

// g-premultiplied hinge derivative + energy
__device__ __forceinline__ Hd hinge_core(float v1x, float v1y,
                                         float v2x, float v2y,
                                         float th, float b0, float b1,
                                         float k_stiff, float k_soft)
{
    float cr = v1x * v2y - v1y * v2x;
    float dt = fmaf(v1x, v2x, v1y * v2y);
    float theta = fast_atan2f(cr, dt);
    bool m0 = fmaf(theta, b0, th) > 0.f;
    bool m1 = fmaf(theta, b1, th) > 0.f;
    float keff = (m0 ? k_stiff : k_soft) + (m1 ? k_stiff : k_soft);
    float diff = theta - th;
    float g = keff * diff;
    float inv = __fdividef(g, fmaf(cr, cr, dt * dt));
    Hd o;
    o.d1x = ( dt * v2y - cr * v2x) * inv;
    o.d1y = (-dt * v2x - cr * v2y) * inv;
    o.d2x = (-dt * v1y - cr * v1x) * inv;
    o.d2y = ( dt * v1x - cr * v1y) * inv;
    o.e   = 0.5f * g * diff;
    return o;
}

__global__ void __launch_bounds__(TPB, 6)
chain_kernel(const float2* __restrict__ pos,
             const float*  __restrict__ th_ss,
             const float*  __restrict__ rest,
             const float*  __restrict__ p_kstiff,
             const float*  __restrict__ p_ksoft,
             const float*  __restrict__ p_kstretch,
             const int2*   __restrict__ buckle,
             float*        __restrict__ out,
             int H, unsigned totalWarps)
{
    const int N = H + 2;
    const int t = blockIdx.x * TPB + threadIdx.x;
    const int s = t * PPT;
    const int lane = threadIdx.x & 31;

    const float k_stiff   = __ldg(p_kstiff);
    const float k_soft    = __ldg(p_ksoft);
    const float k_stretch = __ldg(p_kstretch);

    float rot_e = 0.f, str_e = 0.f;

    // warp-uniform fast/slow decision (shuffles are warp-collective)
    const int ws = ((blockIdx.x * TPB + (threadIdx.x & ~31)) ) * PPT;
    const bool warpFast = (ws >= 2) && (ws + 2 * PPT * 32 + 2 <= N + PPT * 31 * 2)
                          ? ((ws >= 2) && (ws + 32 * PPT + 2 <= N)) : false;

    if (warpFast) {
        // ---------- own aligned loads ----------
        float px[PPT], py[PPT];
        {
            const float4* p4 = (const float4*)(pos + s);
            #pragma unroll
            for (int i = 0; i < 4; i++) {
                float4 v = __ldg(&p4[i]);
                px[2 * i] = v.x; py[2 * i] = v.y;
                px[2 * i + 1] = v.z; py[2 * i + 1] = v.w;
            }
        }
        float TH[PPT], B0[PPT], B1[PPT], RL[PPT];
        {
            float4 a = __ldg((const float4*)(th_ss + s));
            float4 b = __ldg((const float4*)(th_ss + s + 4));
            TH[0]=a.x; TH[1]=a.y; TH[2]=a.z; TH[3]=a.w;
            TH[4]=b.x; TH[5]=b.y; TH[6]=b.z; TH[7]=b.w;
        }
        {
            const int4* b4 = (const int4*)(buckle + s);
            #pragma unroll
            for (int i = 0; i < 4; i++) {
                int4 v = __ldg(&b4[i]);
                B0[2*i]   = (float)v.x; B1[2*i]   = (float)v.y;
                B0[2*i+1] = (float)v.z; B1[2*i+1] = (float)v.w;
            }
        }
        {
            float4 a = __ldg((const float4*)(rest + s));
            float4 b = __ldg((const float4*)(rest + s + 4));
            RL[0]=a.x; RL[1]=a.y; RL[2]=a.z; RL[3]=a.w;
            RL[4]=b.x; RL[5]=b.y; RL[6]=b.z; RL[7]=b.w;
        }

        // boundary-lane extra loads
        float bpx0 = 0.f, bpy0 = 0.f, bpx1 = 0.f, bpy1 = 0.f;   // lane0: pos[s-2], pos[s-1]
        float npx0 = 0.f, npy0 = 0.f, npx1 = 0.f, npy1 = 0.f;   // lane31: pos[s+8], pos[s+9]
        if (lane == 0) {
            float4 v = __ldg((const float4*)(pos + (s - 2)));
            bpx0 = v.x; bpy0 = v.y; bpx1 = v.z; bpy1 = v.w;
        }
        if (lane == 31) {
            float4 v = __ldg((const float4*)(pos + (s + PPT)));
            npx0 = v.x; npy0 = v.y; npx1 = v.z; npy1 = v.w;
        }

        // ---------- edge vectors E[0..8] : edges s .. s+8 ----------
        float ex[9], ey[9];
        #pragma unroll
        for (int k = 0; k < 7; k++) {
            ex[k] = px[k + 1] - px[k];
            ey[k] = py[k + 1] - py[k];
        }
        // edge s+7 : pos[s+8] - pos[s+7]
        {
            float nx = __shfl_down_sync(FULLMASK, px[0], 1);
            float ny = __shfl_down_sync(FULLMASK, py[0], 1);
            if (lane == 31) { nx = npx0; ny = npy0; }
            ex[7] = nx - px[7]; ey[7] = ny - py[7];
        }
        // edge s+8 : neighbor's edge 0
        {
            float nx = __shfl_down_sync(FULLMASK, ex[0], 1);
            float ny = __shfl_down_sync(FULLMASK, ey[0], 1);
            if (lane == 31) { nx = npx1 - npx0; ny = npy1 - npy0; }
            ex[8] = nx; ey[8] = ny;
        }
        // edges s-2, s-1 (lane0 only; other lanes get them from hinge-contrib shfl)
        float em1x = 0.f, em1y = 0.f, em2x = 0.f, em2y = 0.f;
        if (lane == 0) {
            em2x = bpx1 - bpx0;  em2y = bpy1 - bpy0;
            em1x = px[0] - bpx1; em1y = py[0] - bpy1;
        }

        // ---------- 8 own hinges ----------
        float Gx[PPT], Gy[PPT];
        #pragma unroll
        for (int j = 0; j < PPT; j++) { Gx[j] = 0.f; Gy[j] = 0.f; }

        float h6gcx = 0.f, h6gcy = 0.f;
        float h7gbx = 0.f, h7gby = 0.f, h7gcx = 0.f, h7gcy = 0.f;

        #pragma unroll
        for (int k = 0; k < PPT; k++) {
            Hd o = hinge_core(ex[k], ey[k], ex[k + 1], ey[k + 1],
                              TH[k], B0[k], B1[k], k_stiff, k_soft);
            rot_e += o.e;
            Gx[k] -= o.d1x; Gy[k] -= o.d1y;                         // point a
            float gbx = o.d1x - o.d2x, gby = o.d1y - o.d2y;         // point b
            if (k < PPT - 1) { Gx[k + 1] += gbx; Gy[k + 1] += gby; }
            else             { h7gbx = gbx; h7gby = gby; }
            if (k < PPT - 2) { Gx[k + 2] += o.d2x; Gy[k + 2] += o.d2y; } // point c
            else if (k == PPT - 2) { h6gcx = o.d2x; h6gcy = o.d2y; }
            else                   { h7gcx = o.d2x; h7gcy = o.d2y; }
        }

        // receive boundary hinge contributions from lane-1
        {
            float a = __shfl_up_sync(FULLMASK, h6gcx, 1);
            float b = __shfl_up_sync(FULLMASK, h6gcy, 1);
            float c = __shfl_up_sync(FULLMASK, h7gbx, 1);
            float d = __shfl_up_sync(FULLMASK, h7gby, 1);
            float e = __shfl_up_sync(FULLMASK, h7gcx, 1);
            float f = __shfl_up_sync(FULLMASK, h7gcy, 1);
            if (lane == 0) {
                // compute hinges s-2, s-1 locally (halo to previous warp)
                float2 thb; int4 bkb;
                thb = __ldg((const float2*)(th_ss + (s - 2)));
                bkb = __ldg((const int4*)(buckle + (s - 2)));
                Hd hm2 = hinge_core(em2x, em2y, em1x, em1y, thb.x,
                                    (float)bkb.x, (float)bkb.y, k_stiff, k_soft);
                Hd hm1 = hinge_core(em1x, em1y, ex[0], ey[0], thb.y,
                                    (float)bkb.z, (float)bkb.w, k_stiff, k_soft);
                a = hm2.d2x; b = hm2.d2y;                       // gc of hinge s-2
                c = hm1.d1x - hm1.d2x; d = hm1.d1y - hm1.d2y;   // gb of hinge s-1
                e = hm1.d2x; f = hm1.d2y;                       // gc of hinge s-1
            }
            Gx[0] += a + c; Gy[0] += b + d;
            Gx[1] += e;     Gy[1] += f;
        }

        // ---------- 8 own stretch edges (s .. s+7) ----------
        float F7x = 0.f, F7y = 0.f;
        #pragma unroll
        for (int k = 0; k < PPT; k++) {
            float exk = ex[k], eyk = ey[k];
            float lensq = fmaf(exk, exk, eyk * eyk);
            float rsq = rsqrtf(lensq);
            float len = lensq * rsq;
            float dl  = len - RL[k];
            float c   = k_stretch * dl * rsq;
            float fx = c * exk, fy = c * eyk;
            str_e = fmaf(0.5f * k_stretch * dl, dl, str_e);
            Gx[k] -= fx; Gy[k] -= fy;                            // tail point
            if (k < PPT - 1) { Gx[k + 1] += fx; Gy[k + 1] += fy; }
            else             { F7x = fx; F7y = fy; }
        }
        // edge s-1 force onto point s (head)
        {
            float a = __shfl_up_sync(FULLMASK, F7x, 1);
            float b = __shfl_up_sync(FULLMASK, F7y, 1);
            if (lane == 0) {
                float rl = __ldg(&rest[s - 1]);
                float lensq = fmaf(em1x, em1x, em1y * em1y);
                float rsq = rsqrtf(lensq);
                float dl  = lensq * rsq - rl;
                float c   = k_stretch * dl * rsq;
                a = c * em1x; b = c * em1y;
            }
            Gx[0] += a; Gy[0] += b;
        }

        // ---------- force writes (p >= 2 always in fast warps) ----------
        out[3 + 2 * s] = -Gx[0];
        float4* o4 = (float4*)(out + 4 + 2 * s);
        o4[0] = make_float4(-Gy[0], -Gx[1], -Gy[1], -Gx[2]);
        o4[1] = make_float4(-Gy[2], -Gx[3], -Gy[3], -Gx[4]);
        o4[2] = make_float4(-Gy[4], -Gx[5], -Gy[5], -Gx[6]);
        out[16 + 2 * s] = -Gy[6];
        out[17 + 2 * s] = -Gx[7];
        out[18 + 2 * s] = -Gy[7];
    } else if (s < N) {
        // ---------- scalar slow path (boundaries; ~2 warps total) ----------
        float ex[11], ey[11];
        {
            float px[PPT + 4], py[PPT + 4];
            #pragma unroll
            for (int j = 0; j < PPT + 4; j++) {
                int g = max(0, min(s - 2 + j, N - 1));
                float2 v = __ldg(&pos[g]);
                px[j] = v.x; py[j] = v.y;
            }
            #pragma unroll
            for (int j = 0; j < 11; j++) {
                ex[j] = px[j + 1] - px[j];
                ey[j] = py[j + 1] - py[j];
            }
        }
        float Gx[PPT], Gy[PPT];
        #pragma unroll
        for (int j = 0; j < PPT; j++) { Gx[j] = 0.f; Gy[j] = 0.f; }

        #pragma unroll
        for (int i = 0; i < PPT + 2; i++) {
            int h = s - 2 + i;
            bool vh = (h >= 0) && (h < H);
            float th = vh ? __ldg(&th_ss[h]) : 0.f;
            int2 bk = vh ? __ldg(&buckle[h]) : make_int2(0, 0);
            float v1x = vh ? ex[i] : 1.f,     v1y = vh ? ey[i] : 0.f;
            float v2x = vh ? ex[i + 1] : 1.f, v2y = vh ? ey[i + 1] : 0.f;
            Hd o = hinge_core(v1x, v1y, v2x, v2y, th,
                              (float)bk.x, (float)bk.y, k_stiff, k_soft);
            if (!vh) { o.d1x = o.d1y = o.d2x = o.d2y = o.e = 0.f; }
            if (i >= 2) rot_e += o.e;
            if (i >= 2) { Gx[i - 2] -= o.d1x; Gy[i - 2] -= o.d1y; }
            if (i >= 1 && i - 1 < PPT) {
                Gx[i - 1] += o.d1x - o.d2x; Gy[i - 1] += o.d1y - o.d2y;
            }
            if (i < PPT) { Gx[i] += o.d2x; Gy[i] += o.d2y; }
        }

        #pragma unroll
        for (int j = 1; j < 10; j++) {
            int e = s - 2 + j;
            bool ve = (e >= 0) && (e <= H);
            float rl = ve ? __ldg(&rest[e]) : 1.f;
            float exk = ex[j], eyk = ey[j];
            float lensq = fmaf(exk, exk, eyk * eyk);
            lensq = ve ? lensq : 1.f;
            float rsq = rsqrtf(lensq);
            float dl  = ve ? (lensq * rsq - rl) : 0.f;
            float c   = k_stretch * dl * rsq;
            float fx = c * exk, fy = c * eyk;
            if (j >= 2) str_e = fmaf(0.5f * k_stretch * dl, dl, str_e);
            if (j >= 2)      { Gx[j - 2] -= fx; Gy[j - 2] -= fy; }
            if (j - 1 < PPT) { Gx[j - 1] += fx; Gy[j - 1] += fy; }
        }

        #pragma unroll
        for (int j = 0; j < PPT; j++) {
            int p = s + j;
            if (p < N) {
                bool z = (p < 2);
                out[3 + 2 * p]     = z ? 0.f : -Gx[j];
                out[3 + 2 * p + 1] = z ? 0.f : -Gy[j];
            }
        }
    }

    // ---------------- energy reduction ----------------
    float r = rot_e, sv = str_e;
    #pragma unroll
    for (int off = 16; off > 0; off >>= 1) {
        r  += __shfl_down_sync(FULLMASK, r,  off);
        sv += __shfl_down_sync(FULLMASK, sv, off);
    }
    const int wid = threadIdx.x >> 5;
    if (lane == 0) {
        int slot = (blockIdx.x * (TPB / 32) + wid) & 63;
        atomicAdd(&g_rot_acc[slot], (double)r);
        atomicAdd(&g_str_acc[slot], (double)sv);
        __threadfence();
        unsigned tk = atomicAdd(&g_ticket, 1u);
        if (tk == totalWarps - 1u) {
            double R = 0.0, S = 0.0;
            #pragma unroll
            for (int i = 0; i < 64; i++) {
                R += g_rot_acc[i]; g_rot_acc[i] = 0.0;
                S += g_str_acc[i]; g_str_acc[i] = 0.0;
            }
            out[0] = (float)(R + S);
            out[1] = (float)R;
            out[2] = (float)S;
            g_ticket = 0u;
        }
    }
}

extern "C" void kernel_launch(void* const* d_in, const int* in_sizes, int n_in,
                              void* d_out, int out_size) {
    const float2* pos      = (const float2*)d_in[0];
    const float*  th_ss    = (const float*)d_in[1];
    const float*  rest     = (const float*)d_in[2];
    const float*  kstiff   = (const float*)d_in[3];
    const float*  ksoft    = (const float*)d_in[4];
    const float*  kstretch = (const float*)d_in[5];
    const int2*   buckle   = (const int2*)d_in[6];
    float* out = (float*)d_out;

    const int H = in_sizes[1];
    const int N = H + 2;
    const int threads_needed = (N + PPT - 1) / PPT;
    const int blocks = (threads_needed + TPB - 1) / TPB;
    const unsigned totalWarps = (unsigned)blocks * (TPB / 32);

    chain_kernel<<<blocks, TPB>>>(pos, th_ss, rest, kstiff, ksoft, kstretch,
                                  buckle, out, H, totalWarps);
}